// round 4
// baseline (speedup 1.0000x reference)
#include <cuda_runtime.h>

#define D        128
#define NMAX     8192
#define BI       128
#define BJ       128
#define KC       32
#define JSPLIT   4
#define MARGIN_F 0.3f
#define BIGF     1e30f

// Scratch (device globals: no allocations allowed in kernel_launch)
__device__ float g_sq[NMAX];
__device__ int   g_hp[NMAX];   // float bits, hardest positive (max), init -1.0f
__device__ int   g_hn[NMAX];   // float bits, hardest negative (min), init BIGF

__global__ void init_kernel(int n) {
    int i = blockIdx.x * blockDim.x + threadIdx.x;
    if (i < n) {
        g_hp[i] = __float_as_int(-1.0f);
        g_hn[i] = __float_as_int(BIGF);
    }
}

// One warp per row: ||x_i||^2
__global__ void norms_kernel(const float* __restrict__ x, int n) {
    int row  = blockIdx.x * (blockDim.x >> 5) + (threadIdx.x >> 5);
    int lane = threadIdx.x & 31;
    if (row < n) {
        float4 v = reinterpret_cast<const float4*>(x + (size_t)row * D)[lane];
        float s = v.x * v.x + v.y * v.y + v.z * v.z + v.w * v.w;
        #pragma unroll
        for (int o = 16; o; o >>= 1) s += __shfl_xor_sync(0xffffffffu, s, o);
        if (lane == 0) g_sq[row] = s;
    }
}

// Fused Gram-tile + masked hardest-pos/neg epilogue.
// Block: 256 threads = 16x16, each thread owns an 8x8 accumulator tile.
// Grid: (n/BI, JSPLIT). Each block covers rows [i0, i0+128) x a quarter of j-tiles.
__global__ __launch_bounds__(256, 2)
void tile_kernel(const float* __restrict__ x, const int* __restrict__ labels, int n) {
    __shared__ float As[KC][BI];   // transposed: As[k][row]
    __shared__ float Bs[KC][BJ];   // transposed: Bs[k][col]
    __shared__ float sqA[BI];
    __shared__ float sqB[BJ];
    __shared__ int   lbA[BI];
    __shared__ int   lbB[BJ];

    const int tid = threadIdx.x;
    const int tx  = tid & 15;    // column group
    const int ty  = tid >> 4;    // row group
    const int i0  = blockIdx.x * BI;

    const int ntiles = n / BJ;
    const int per    = ntiles / JSPLIT;
    const int jt0    = blockIdx.y * per;

    if (tid < BI) {
        sqA[tid] = g_sq[i0 + tid];
        lbA[tid] = labels[i0 + tid];
    }

    float hp[8], hn[8];
    #pragma unroll
    for (int m = 0; m < 8; m++) { hp[m] = -1.0f; hn[m] = BIGF; }

    // Global->smem loader mapping: each thread loads 4 float4 per tile
    const int lrow = tid >> 3;         // 0..31 (base row, +32*q)
    const int lcol = (tid & 7) * 4;    // 0,4,...,28 (k offset within chunk)

    for (int jt = jt0; jt < jt0 + per; jt++) {
        const int j0 = jt * BJ;
        __syncthreads();  // prior epilogue done reading sqB/lbB
        if (tid < BJ) {
            sqB[tid] = g_sq[j0 + tid];
            lbB[tid] = labels[j0 + tid];
        }

        float acc[8][8];
        #pragma unroll
        for (int m = 0; m < 8; m++)
            #pragma unroll
            for (int nn = 0; nn < 8; nn++) acc[m][nn] = 0.0f;

        for (int kc = 0; kc < D; kc += KC) {
            float4 av[4], bv[4];
            #pragma unroll
            for (int q = 0; q < 4; q++) {
                av[q] = *reinterpret_cast<const float4*>(
                    x + (size_t)(i0 + lrow + q * 32) * D + kc + lcol);
                bv[q] = *reinterpret_cast<const float4*>(
                    x + (size_t)(j0 + lrow + q * 32) * D + kc + lcol);
            }
            __syncthreads();  // prior compute done reading tiles
            #pragma unroll
            for (int q = 0; q < 4; q++) {
                const int r = lrow + q * 32;
                As[lcol + 0][r] = av[q].x;
                As[lcol + 1][r] = av[q].y;
                As[lcol + 2][r] = av[q].z;
                As[lcol + 3][r] = av[q].w;
                Bs[lcol + 0][r] = bv[q].x;
                Bs[lcol + 1][r] = bv[q].y;
                Bs[lcol + 2][r] = bv[q].z;
                Bs[lcol + 3][r] = bv[q].w;
            }
            __syncthreads();

            #pragma unroll
            for (int kk = 0; kk < KC; kk++) {
                float4 a0 = *reinterpret_cast<const float4*>(&As[kk][ty * 8]);
                float4 a1 = *reinterpret_cast<const float4*>(&As[kk][ty * 8 + 4]);
                float4 b0 = *reinterpret_cast<const float4*>(&Bs[kk][tx * 8]);
                float4 b1 = *reinterpret_cast<const float4*>(&Bs[kk][tx * 8 + 4]);
                float a[8] = {a0.x, a0.y, a0.z, a0.w, a1.x, a1.y, a1.z, a1.w};
                float b[8] = {b0.x, b0.y, b0.z, b0.w, b1.x, b1.y, b1.z, b1.w};
                #pragma unroll
                for (int m = 0; m < 8; m++)
                    #pragma unroll
                    for (int nn = 0; nn < 8; nn++)
                        acc[m][nn] = fmaf(a[m], b[nn], acc[m][nn]);
            }
        }

        // Epilogue: d = sqrt(max(sq_i + sq_j - 2*dot, 0)), masked max/min
        #pragma unroll
        for (int m = 0; m < 8; m++) {
            const int   r  = i0 + ty * 8 + m;
            const float sa = sqA[ty * 8 + m];
            const int   la = lbA[ty * 8 + m];
            #pragma unroll
            for (int nn = 0; nn < 8; nn++) {
                const int   c  = j0 + tx * 8 + nn;
                const float d2 = sa + sqB[tx * 8 + nn] - 2.0f * acc[m][nn];
                const float d  = sqrtf(fmaxf(d2, 0.0f));
                const bool same = (la == lbB[tx * 8 + nn]);
                if (same) {
                    if (r != c) hp[m] = fmaxf(hp[m], d);
                } else {
                    hn[m] = fminf(hn[m], d);
                }
            }
        }
    }

    // Reduce across the 16 tx-lanes (half-warp: lanes with same ty) then one atomic.
    // All candidate distances >= 0, so float-as-signed-int ordering is monotone.
    #pragma unroll
    for (int m = 0; m < 8; m++) {
        float vp = hp[m], vn = hn[m];
        #pragma unroll
        for (int o = 1; o < 16; o <<= 1) {
            vp = fmaxf(vp, __shfl_xor_sync(0xffffffffu, vp, o));
            vn = fminf(vn, __shfl_xor_sync(0xffffffffu, vn, o));
        }
        if (tx == 0) {
            atomicMax(&g_hp[i0 + ty * 8 + m], __float_as_int(vp));
            atomicMin(&g_hn[i0 + ty * 8 + m], __float_as_int(vn));
        }
    }
}

// Deterministic single-block final reduction.
__global__ void finalize_kernel(float* __restrict__ out, int n) {
    __shared__ float ssum[256];
    __shared__ float scnt[256];
    const int tid = threadIdx.x;
    float sum = 0.0f, cnt = 0.0f;
    for (int i = tid; i < n; i += 256) {
        const float hpv = __int_as_float(g_hp[i]);
        const float hnv = __int_as_float(g_hn[i]);
        if (hpv >= 0.0f && hnv < 0.5f * BIGF) {
            sum += fmaxf(hpv - hnv + MARGIN_F, 0.0f);
            cnt += 1.0f;
        }
    }
    ssum[tid] = sum;
    scnt[tid] = cnt;
    __syncthreads();
    for (int s = 128; s; s >>= 1) {
        if (tid < s) {
            ssum[tid] += ssum[tid + s];
            scnt[tid] += scnt[tid + s];
        }
        __syncthreads();
    }
    if (tid == 0) out[0] = (scnt[0] > 0.0f) ? (ssum[0] / scnt[0]) : 0.0f;
}

extern "C" void kernel_launch(void* const* d_in, const int* in_sizes, int n_in,
                              void* d_out, int out_size) {
    const float* x      = (const float*)d_in[0];
    const int*   labels = (const int*)d_in[1];
    const int    n      = in_sizes[1];   // 8192
    float*       out    = (float*)d_out;

    init_kernel<<<(n + 255) / 256, 256>>>(n);
    norms_kernel<<<n / 8, 256>>>(x, n);   // 8 warps/block = 8 rows/block

    dim3 grid(n / BI, JSPLIT);
    tile_kernel<<<grid, 256>>>(x, labels, n);

    finalize_kernel<<<1, 256>>>(out, n);
}

// round 9
// speedup vs baseline: 5.8865x; 5.8865x over previous
#include <cuda_runtime.h>
#include <cuda_fp16.h>

#define D        128
#define NMAX     8192
#define TILE     128
#define JS       2
#define MARGIN_F 0.3f
#define BIGF     1e30f

// ---------------- device global scratch ----------------
__device__ float  g_sq[NMAX];
__device__ int    g_hp[NMAX];            // float bits of max d2 (pos)
__device__ int    g_hn[NMAX];            // float bits of min d2 (neg)
__device__ __half g_xh[NMAX * D];

// ---------------- smem layout (bytes) ----------------
#define ROWB       272                    // 128 halves + 8 pad = 136*2
#define TILE_BYTES (TILE * ROWB)          // 34816
#define OFF_AS     0
#define OFF_BS0    TILE_BYTES
#define OFF_BS1    (2 * TILE_BYTES)
#define OFF_SQB0   (3 * TILE_BYTES)                // 512 f32
#define OFF_LBB0   (3 * TILE_BYTES + 512)
#define OFF_SQB1   (3 * TILE_BYTES + 1024)
#define OFF_LBB1   (3 * TILE_BYTES + 1536)
#define SMEM_DYN   (3 * TILE_BYTES + 2048)

// ---------------- PTX helpers ----------------
__device__ __forceinline__ unsigned smem_u32(const void* p) {
    unsigned a;
    asm("{ .reg .u64 t; cvta.to.shared.u64 t, %1; cvt.u32.u64 %0, t; }" : "=r"(a) : "l"(p));
    return a;
}
__device__ __forceinline__ void cp16(unsigned dst, const void* src) {
    asm volatile("cp.async.cg.shared.global [%0], [%1], 16;" :: "r"(dst), "l"(src));
}
__device__ __forceinline__ void cp4(unsigned dst, const void* src) {
    asm volatile("cp.async.ca.shared.global [%0], [%1], 4;" :: "r"(dst), "l"(src));
}
#define CP_COMMIT() asm volatile("cp.async.commit_group;" ::: "memory")
#define CP_WAIT0()  asm volatile("cp.async.wait_group 0;" ::: "memory")

__device__ __forceinline__ void ldsm_x4(unsigned r[4], unsigned addr) {
    asm volatile("ldmatrix.sync.aligned.m8n8.x4.shared.b16 {%0,%1,%2,%3}, [%4];"
                 : "=r"(r[0]), "=r"(r[1]), "=r"(r[2]), "=r"(r[3]) : "r"(addr));
}
__device__ __forceinline__ void mma16816(float c[4], const unsigned a[4],
                                         unsigned b0, unsigned b1) {
    asm volatile(
        "mma.sync.aligned.m16n8k16.row.col.f32.f16.f16.f32 "
        "{%0,%1,%2,%3}, {%4,%5,%6,%7}, {%8,%9}, {%0,%1,%2,%3};"
        : "+f"(c[0]), "+f"(c[1]), "+f"(c[2]), "+f"(c[3])
        : "r"(a[0]), "r"(a[1]), "r"(a[2]), "r"(a[3]), "r"(b0), "r"(b1));
}

// ---------------- small kernels ----------------
// convert x -> fp16, and init g_hp/g_hn (folded in)
__global__ void convert_kernel(const float* __restrict__ x, int n) {
    int i = blockIdx.x * blockDim.x + threadIdx.x;
    int total4 = n * D / 4;
    if (i < total4) {
        float4 v = reinterpret_cast<const float4*>(x)[i];
        __half2 h0 = __floats2half2_rn(v.x, v.y);
        __half2 h1 = __floats2half2_rn(v.z, v.w);
        uint2 o;
        o.x = *reinterpret_cast<unsigned*>(&h0);
        o.y = *reinterpret_cast<unsigned*>(&h1);
        reinterpret_cast<uint2*>(g_xh)[i] = o;
    }
    if (i < n) {
        g_hp[i] = __float_as_int(-1.0f);
        g_hn[i] = __float_as_int(BIGF);
    }
}

// norms of the ROUNDED vectors (so d2 is exact for x-hat)
__global__ void norms_kernel(int n) {
    int row  = blockIdx.x * (blockDim.x >> 5) + (threadIdx.x >> 5);
    int lane = threadIdx.x & 31;
    if (row < n) {
        uint2 v = reinterpret_cast<const uint2*>(g_xh + (size_t)row * D)[lane];
        __half2 a = *reinterpret_cast<__half2*>(&v.x);
        __half2 b = *reinterpret_cast<__half2*>(&v.y);
        float2 fa = __half22float2(a), fb = __half22float2(b);
        float s = fa.x * fa.x + fa.y * fa.y + fb.x * fb.x + fb.y * fb.y;
        #pragma unroll
        for (int o = 16; o; o >>= 1) s += __shfl_xor_sync(0xffffffffu, s, o);
        if (lane == 0) g_sq[row] = s;
    }
}

// ---------------- main HMMA Gram kernel ----------------
__device__ __forceinline__ void prefetch_tile(char* dyn, unsigned dynb, int off_tile,
                                              int off_sq, int off_lb,
                                              const int* __restrict__ labels,
                                              int r0, int tid, bool scalars) {
    #pragma unroll
    for (int it = 0; it < 8; it++) {
        int c   = tid + it * 256;        // 2048 16B chunks
        int row = c >> 4;
        int j2  = c & 15;
        cp16(dynb + off_tile + row * ROWB + j2 * 16,
             g_xh + (size_t)(r0 + row) * D + j2 * 8);
    }
    if (scalars && tid < TILE) {
        cp4(dynb + off_sq + tid * 4, &g_sq[r0 + tid]);
        cp4(dynb + off_lb + tid * 4, &labels[r0 + tid]);
    }
}

__global__ __launch_bounds__(256, 1)
void gram_kernel(const int* __restrict__ labels, int n) {
    extern __shared__ char dyn[];
    const unsigned dynb = smem_u32(dyn);

    const int tid  = threadIdx.x;
    const int warp = tid >> 5, lane = tid & 31;
    const int wm   = warp & 1;           // 0..1 : rows  wm*64 + ...
    const int wn   = warp >> 1;          // 0..3 : cols  wn*32 + ...

    const int i0  = blockIdx.x * TILE;
    const int nj  = (n / TILE) / JS;
    const int jt0 = blockIdx.y * nj;

    // prologue: A tile + B tile 0 (+ its scalars)
    prefetch_tile(dyn, dynb, OFF_AS, 0, 0, labels, i0, tid, false);
    prefetch_tile(dyn, dynb, OFF_BS0, OFF_SQB0, OFF_LBB0, labels, jt0 * TILE, tid, true);
    CP_COMMIT();

    // per-thread A-side constants: 8 rows = (mt 0..3) x (h 0..1)
    float sa_r[8];
    int   la_r[8];
    const int rbase = i0 + wm * 64 + (lane >> 2);
    #pragma unroll
    for (int q = 0; q < 8; q++) {
        int r = rbase + (q >> 1) * 16 + (q & 1) * 8;
        sa_r[q] = g_sq[r];
        la_r[q] = labels[r];
    }

    float hp2[8], hn2[8];
    #pragma unroll
    for (int q = 0; q < 8; q++) { hp2[q] = -1.0f; hn2[q] = BIGF; }

    // ldmatrix base offsets (per-lane)
    const unsigned a_row = (unsigned)(wm * 64 + (lane & 15));
    const unsigned a_kad = (unsigned)((lane >> 4) * 16);             // bytes: 8 halves
    const unsigned b_row = (unsigned)(wn * 32 + ((lane >> 4) << 3) + (lane & 7));
    const unsigned b_kad = (unsigned)(((lane >> 3) & 1) * 16);

    for (int t = 0; t < nj; t++) {
        CP_WAIT0();
        __syncthreads();
        const int buf      = t & 1;
        const int off_bs   = buf ? OFF_BS1 : OFF_BS0;
        const int off_sqb  = buf ? OFF_SQB1 : OFF_SQB0;
        const int off_lbb  = buf ? OFF_LBB1 : OFF_LBB0;

        if (t + 1 < nj)
            prefetch_tile(dyn, dynb, buf ? OFF_BS0 : OFF_BS1,
                          buf ? OFF_SQB0 : OFF_SQB1, buf ? OFF_LBB0 : OFF_LBB1,
                          labels, (jt0 + t + 1) * TILE, tid, true);
        CP_COMMIT();

        // ---- MMA: 128x128 tile, K=128 ----
        float acc[4][4][4];
        #pragma unroll
        for (int mt = 0; mt < 4; mt++)
            #pragma unroll
            for (int nt = 0; nt < 4; nt++)
                #pragma unroll
                for (int r = 0; r < 4; r++) acc[mt][nt][r] = 0.0f;

        #pragma unroll
        for (int ks = 0; ks < 8; ks++) {
            const unsigned kb = (unsigned)(ks * 32);   // 16 halves = 32 bytes
            unsigned a[4][4];
            #pragma unroll
            for (int mt = 0; mt < 4; mt++)
                ldsm_x4(a[mt], dynb + OFF_AS + (a_row + mt * 16) * ROWB + kb + a_kad);
            unsigned b[2][4];
            #pragma unroll
            for (int bp = 0; bp < 2; bp++)
                ldsm_x4(b[bp], dynb + off_bs + (b_row + bp * 16) * ROWB + kb + b_kad);
            #pragma unroll
            for (int mt = 0; mt < 4; mt++)
                #pragma unroll
                for (int nt = 0; nt < 4; nt++)
                    mma16816(acc[mt][nt], a[mt],
                             b[nt >> 1][(nt & 1) * 2], b[nt >> 1][(nt & 1) * 2 + 1]);
        }

        // ---- fused epilogue on register fragments ----
        const float* sqB = reinterpret_cast<const float*>(dyn + off_sqb);
        const int*   lbB = reinterpret_cast<const int*>(dyn + off_lbb);
        float sb[8]; int lbr[8];
        #pragma unroll
        for (int nt = 0; nt < 4; nt++)
            #pragma unroll
            for (int u = 0; u < 2; u++) {
                int cl = wn * 32 + nt * 8 + 2 * (lane & 3) + u;
                sb[nt * 2 + u]  = sqB[cl];
                lbr[nt * 2 + u] = lbB[cl];
            }
        const int j0g = (jt0 + t) * TILE;
        #pragma unroll
        for (int mt = 0; mt < 4; mt++) {
            #pragma unroll
            for (int h = 0; h < 2; h++) {
                const int   q  = mt * 2 + h;
                const float sa = sa_r[q];
                const int   la = la_r[q];
                const int   ig = rbase + mt * 16 + h * 8;
                #pragma unroll
                for (int nt = 0; nt < 4; nt++) {
                    #pragma unroll
                    for (int u = 0; u < 2; u++) {
                        const float dot = acc[mt][nt][h * 2 + u];
                        const float d2  = fmaxf(fmaf(-2.0f, dot, sa + sb[nt * 2 + u]), 0.0f);
                        const int   cl  = wn * 32 + nt * 8 + 2 * (lane & 3) + u;
                        if (j0g + cl != ig) {
                            if (lbr[nt * 2 + u] == la) hp2[q] = fmaxf(hp2[q], d2);
                            else                       hn2[q] = fminf(hn2[q], d2);
                        }
                    }
                }
            }
        }
    }

    // ---- reduce across the 4 lanes of each row-quad, then atomics ----
    #pragma unroll
    for (int q = 0; q < 8; q++) {
        float vp = hp2[q], vn = hn2[q];
        vp = fmaxf(vp, __shfl_xor_sync(0xffffffffu, vp, 1));
        vp = fmaxf(vp, __shfl_xor_sync(0xffffffffu, vp, 2));
        vn = fminf(vn, __shfl_xor_sync(0xffffffffu, vn, 1));
        vn = fminf(vn, __shfl_xor_sync(0xffffffffu, vn, 2));
        if ((lane & 3) == 0) {
            const int r = rbase + (q >> 1) * 16 + (q & 1) * 8;
            atomicMax(&g_hp[r], __float_as_int(vp));   // d2 >= 0: int order == float order
            atomicMin(&g_hn[r], __float_as_int(vn));
        }
    }
}

// ---------------- finalize: sqrt + masked mean (deterministic) ----------------
__global__ void finalize_kernel(float* __restrict__ out, int n) {
    __shared__ float ssum[1024];
    __shared__ float scnt[1024];
    const int tid = threadIdx.x;
    float sum = 0.0f, cnt = 0.0f;
    for (int i = tid; i < n; i += 1024) {
        const float hp2 = __int_as_float(g_hp[i]);
        const float hn2 = __int_as_float(g_hn[i]);
        if (hp2 >= 0.0f && hn2 < 0.5f * BIGF) {
            sum += fmaxf(sqrtf(hp2) - sqrtf(hn2) + MARGIN_F, 0.0f);
            cnt += 1.0f;
        }
    }
    ssum[tid] = sum; scnt[tid] = cnt;
    __syncthreads();
    for (int s = 512; s; s >>= 1) {
        if (tid < s) { ssum[tid] += ssum[tid + s]; scnt[tid] += scnt[tid + s]; }
        __syncthreads();
    }
    if (tid == 0) out[0] = (scnt[0] > 0.0f) ? (ssum[0] / scnt[0]) : 0.0f;
}

extern "C" void kernel_launch(void* const* d_in, const int* in_sizes, int n_in,
                              void* d_out, int out_size) {
    const float* x      = (const float*)d_in[0];
    const int*   labels = (const int*)d_in[1];
    const int    n      = in_sizes[1];     // 8192
    float*       out    = (float*)d_out;

    static bool attr_set = false;          // idempotent attribute opt-in
    if (!attr_set) {
        cudaFuncSetAttribute(gram_kernel,
                             cudaFuncAttributeMaxDynamicSharedMemorySize, SMEM_DYN);
        attr_set = true;
    }

    convert_kernel<<<(n * D / 4 + 255) / 256, 256>>>(x, n);
    norms_kernel<<<n / 8, 256>>>(n);

    dim3 grid(n / TILE, JS);
    gram_kernel<<<grid, 256, SMEM_DYN>>>(labels, n);

    finalize_kernel<<<1, 1024>>>(out, n);
}

// round 12
// speedup vs baseline: 8.4457x; 1.4348x over previous
#include <cuda_runtime.h>
#include <cuda_fp16.h>

#define D        128
#define NMAX     8192
#define TILE     128
#define MARGIN_F 0.3f
#define BIGF     1e30f

// ---------------- device global scratch ----------------
__device__ float  g_sq[NMAX];
__device__ int    g_hp[NMAX];            // float bits of max d2 (pos)
__device__ int    g_hn[NMAX];            // float bits of min d2 (neg)
__device__ __half g_xh[NMAX * D];
__device__ unsigned g_done;

// ---------------- smem layout (bytes) ----------------
#define ROWB       272                    // 128 halves + 8 pad halves
#define TB         (TILE * ROWB)          // 34816
#define OFF_A      0
#define OFF_B0     TB
#define OFF_B1     (2 * TB)
#define OFF_SQ0    (3 * TB)
#define OFF_LB0    (3 * TB + 512)
#define OFF_SQ1    (3 * TB + 1024)
#define OFF_LB1    (3 * TB + 1536)
#define SMEM_DYN   (3 * TB + 2048)

// ---------------- PTX helpers ----------------
__device__ __forceinline__ unsigned smem_u32(const void* p) {
    unsigned a;
    asm("{ .reg .u64 t; cvta.to.shared.u64 t, %1; cvt.u32.u64 %0, t; }" : "=r"(a) : "l"(p));
    return a;
}
__device__ __forceinline__ void cp16(unsigned dst, const void* src) {
    asm volatile("cp.async.cg.shared.global [%0], [%1], 16;" :: "r"(dst), "l"(src));
}
__device__ __forceinline__ void cp4(unsigned dst, const void* src) {
    asm volatile("cp.async.ca.shared.global [%0], [%1], 4;" :: "r"(dst), "l"(src));
}
#define CP_COMMIT() asm volatile("cp.async.commit_group;" ::: "memory")
#define CP_WAIT0()  asm volatile("cp.async.wait_group 0;" ::: "memory")

__device__ __forceinline__ void ldsm_x4(unsigned r[4], unsigned addr) {
    asm volatile("ldmatrix.sync.aligned.m8n8.x4.shared.b16 {%0,%1,%2,%3}, [%4];"
                 : "=r"(r[0]), "=r"(r[1]), "=r"(r[2]), "=r"(r[3]) : "r"(addr));
}
__device__ __forceinline__ void mma16816(float c[4], const unsigned a[4],
                                         unsigned b0, unsigned b1) {
    asm volatile(
        "mma.sync.aligned.m16n8k16.row.col.f32.f16.f16.f32 "
        "{%0,%1,%2,%3}, {%4,%5,%6,%7}, {%8,%9}, {%0,%1,%2,%3};"
        : "+f"(c[0]), "+f"(c[1]), "+f"(c[2]), "+f"(c[3])
        : "r"(a[0]), "r"(a[1]), "r"(a[2]), "r"(a[3]), "r"(b0), "r"(b1));
}

// ---------------- convert + norms + init, one kernel (warp per row) ----------
__global__ void convert_kernel(const float* __restrict__ x, int n) {
    const int row  = blockIdx.x * 8 + (threadIdx.x >> 5);
    const int lane = threadIdx.x & 31;
    if (blockIdx.x == 0 && threadIdx.x == 0) g_done = 0;
    if (row < n) {
        float4 v = reinterpret_cast<const float4*>(x + (size_t)row * D)[lane];
        __half2 h0 = __floats2half2_rn(v.x, v.y);
        __half2 h1 = __floats2half2_rn(v.z, v.w);
        uint2 o;
        o.x = *reinterpret_cast<unsigned*>(&h0);
        o.y = *reinterpret_cast<unsigned*>(&h1);
        reinterpret_cast<uint2*>(g_xh + (size_t)row * D)[lane] = o;
        float2 fa = __half22float2(h0), fb = __half22float2(h1);
        float s = fa.x * fa.x + fa.y * fa.y + fb.x * fb.x + fb.y * fb.y;
        #pragma unroll
        for (int o2 = 16; o2; o2 >>= 1) s += __shfl_xor_sync(0xffffffffu, s, o2);
        if (lane == 0) {
            g_sq[row] = s;
            g_hp[row] = __float_as_int(-1.0f);
            g_hn[row] = __float_as_int(BIGF);
        }
    }
}

// ---------------- tile prefetch ----------------
__device__ __forceinline__ void prefetch_tile(unsigned dynb, int off_tile,
                                              int off_sq, int off_lb,
                                              const int* __restrict__ labels,
                                              int r0, int tid, bool scalars) {
    #pragma unroll
    for (int it = 0; it < 8; it++) {
        int c   = tid + it * 256;
        int row = c >> 4;
        int j2  = c & 15;
        cp16(dynb + off_tile + row * ROWB + j2 * 16,
             g_xh + (size_t)(r0 + row) * D + j2 * 8);
    }
    if (scalars && tid < TILE) {
        cp4(dynb + off_sq + tid * 4, &g_sq[r0 + tid]);
        cp4(dynb + off_lb + tid * 4, &labels[r0 + tid]);
    }
}

// ---------------- main persistent HMMA kernel (upper triangle) -------------
__global__ __launch_bounds__(256, 1)
void gram_kernel(const int* __restrict__ labels, int n, float* __restrict__ out) {
    extern __shared__ char dyn[];
    const unsigned dynb = smem_u32(dyn);

    const int tid  = threadIdx.x;
    const int warp = tid >> 5, lane = tid & 31;
    const int wm   = warp & 1;
    const int wn   = warp >> 1;

    const int NTl   = n / TILE;
    const int total = NTl * (NTl + 1) / 2;
    const int start = (int)((long long)blockIdx.x * total / gridDim.x);
    const int end   = (int)((long long)(blockIdx.x + 1) * total / gridDim.x);

    float hp2[8], hn2[8];
    #pragma unroll
    for (int q = 0; q < 8; q++) { hp2[q] = -1.0f; hn2[q] = BIGF; }

    float sa_r[8];
    int   la_r[8];

    int it = 0, jt = 0;
    if (start < end) {
        int rem = start;
        while (rem >= NTl - it) { rem -= NTl - it; it++; }
        jt = it + rem;

        prefetch_tile(dynb, OFF_A, 0, 0, labels, it * TILE, tid, false);
        prefetch_tile(dynb, OFF_B0, OFF_SQ0, OFF_LB0, labels, jt * TILE, tid, true);
        CP_COMMIT();

        const int rb = it * TILE + wm * 64 + (lane >> 2);
        #pragma unroll
        for (int q = 0; q < 8; q++) {
            int r = rb + (q >> 1) * 16 + (q & 1) * 8;
            sa_r[q] = g_sq[r];
            la_r[q] = labels[r];
        }
    }

    const unsigned a_row = (unsigned)(wm * 64 + (lane & 15));
    const unsigned a_kad = (unsigned)((lane >> 4) * 16);
    const unsigned b_row = (unsigned)(wn * 32 + ((lane >> 4) << 3) + (lane & 7));
    const unsigned b_kad = (unsigned)(((lane >> 3) & 1) * 16);

    for (int k = start; k < end; k++) {
        // next tile coords
        int it2 = it, jt2 = jt + 1;
        if (jt2 == NTl) { it2 = it + 1; jt2 = it2; }

        CP_WAIT0();
        __syncthreads();
        const int buf     = (k - start) & 1;
        const int off_bs  = buf ? OFF_B1 : OFF_B0;
        const int off_sqb = buf ? OFF_SQ1 : OFF_SQ0;
        const int off_lbb = buf ? OFF_LB1 : OFF_LB0;

        if (k + 1 < end) {
            prefetch_tile(dynb, buf ? OFF_B0 : OFF_B1,
                          buf ? OFF_SQ0 : OFF_SQ1, buf ? OFF_LB0 : OFF_LB1,
                          labels, jt2 * TILE, tid, true);
            CP_COMMIT();
        }

        // ---- MMA: 128x128 tile, K=128 ----
        float acc[4][4][4];
        #pragma unroll
        for (int mt = 0; mt < 4; mt++)
            #pragma unroll
            for (int nt = 0; nt < 4; nt++)
                #pragma unroll
                for (int r = 0; r < 4; r++) acc[mt][nt][r] = 0.0f;

        #pragma unroll
        for (int ks = 0; ks < 8; ks++) {
            const unsigned kb = (unsigned)(ks * 32);
            unsigned a[4][4];
            #pragma unroll
            for (int mt = 0; mt < 4; mt++)
                ldsm_x4(a[mt], dynb + OFF_A + (a_row + mt * 16) * ROWB + kb + a_kad);
            unsigned b[2][4];
            #pragma unroll
            for (int bp = 0; bp < 2; bp++)
                ldsm_x4(b[bp], dynb + off_bs + (b_row + bp * 16) * ROWB + kb + b_kad);
            #pragma unroll
            for (int mt = 0; mt < 4; mt++)
                #pragma unroll
                for (int nt = 0; nt < 4; nt++)
                    mma16816(acc[mt][nt], a[mt],
                             b[nt >> 1][(nt & 1) * 2], b[nt >> 1][(nt & 1) * 2 + 1]);
        }

        // ---- epilogue ----
        const float* sqB = reinterpret_cast<const float*>(dyn + off_sqb);
        const int*   lbB = reinterpret_cast<const int*>(dyn + off_lbb);
        float sb[8]; int lbr[8];
        #pragma unroll
        for (int nt = 0; nt < 4; nt++)
            #pragma unroll
            for (int u = 0; u < 2; u++) {
                int cl = wn * 32 + nt * 8 + 2 * (lane & 3) + u;
                sb[nt * 2 + u]  = sqB[cl];
                lbr[nt * 2 + u] = lbB[cl];
            }
        const int rbase = it * TILE + wm * 64 + (lane >> 2);
        const int j0g   = jt * TILE;

        if (it == jt) {
            // diagonal: row-side only, mask self pairs
            #pragma unroll
            for (int mt = 0; mt < 4; mt++)
                #pragma unroll
                for (int h = 0; h < 2; h++) {
                    const int   q  = mt * 2 + h;
                    const float sa = sa_r[q];
                    const int   la = la_r[q];
                    const int   ig = rbase + mt * 16 + h * 8;
                    #pragma unroll
                    for (int nt = 0; nt < 4; nt++)
                        #pragma unroll
                        for (int u = 0; u < 2; u++) {
                            const float d2 = fmaxf(
                                fmaf(-2.0f, acc[mt][nt][h * 2 + u], sa + sb[nt * 2 + u]), 0.0f);
                            const int cl = wn * 32 + nt * 8 + 2 * (lane & 3) + u;
                            if (j0g + cl != ig) {
                                if (lbr[nt * 2 + u] == la) hp2[q] = fmaxf(hp2[q], d2);
                                else                       hn2[q] = fminf(hn2[q], d2);
                            }
                        }
                }
        } else {
            // off-diagonal: row-side registers + column-side reduce/atomics
            float cp2[8], cn2[8];
            #pragma unroll
            for (int e = 0; e < 8; e++) { cp2[e] = -1.0f; cn2[e] = BIGF; }
            #pragma unroll
            for (int mt = 0; mt < 4; mt++)
                #pragma unroll
                for (int h = 0; h < 2; h++) {
                    const int   q  = mt * 2 + h;
                    const float sa = sa_r[q];
                    const int   la = la_r[q];
                    #pragma unroll
                    for (int nt = 0; nt < 4; nt++)
                        #pragma unroll
                        for (int u = 0; u < 2; u++) {
                            const int   e  = nt * 2 + u;
                            const float d2 = fmaxf(
                                fmaf(-2.0f, acc[mt][nt][h * 2 + u], sa + sb[e]), 0.0f);
                            if (lbr[e] == la) {
                                hp2[q] = fmaxf(hp2[q], d2);
                                cp2[e] = fmaxf(cp2[e], d2);
                            } else {
                                hn2[q] = fminf(hn2[q], d2);
                                cn2[e] = fminf(cn2[e], d2);
                            }
                        }
                }
            // reduce col-side over the 8 row-lanes (stride 4,8,16)
            #pragma unroll
            for (int s = 4; s <= 16; s <<= 1)
                #pragma unroll
                for (int e = 0; e < 8; e++) {
                    cp2[e] = fmaxf(cp2[e], __shfl_xor_sync(0xffffffffu, cp2[e], s));
                    cn2[e] = fminf(cn2[e], __shfl_xor_sync(0xffffffffu, cn2[e], s));
                }
            if ((lane >> 2) == 0) {
                #pragma unroll
                for (int nt = 0; nt < 4; nt++)
                    #pragma unroll
                    for (int u = 0; u < 2; u++) {
                        const int col = j0g + wn * 32 + nt * 8 + 2 * lane + u;
                        atomicMax(&g_hp[col], __float_as_int(cp2[nt * 2 + u]));
                        atomicMin(&g_hn[col], __float_as_int(cn2[nt * 2 + u]));
                    }
            }
        }

        // i-tile change: flush row-side, reload A + row scalars
        if (k + 1 < end && it2 != it) {
            #pragma unroll
            for (int q = 0; q < 8; q++) {
                float vp = hp2[q], vn = hn2[q];
                vp = fmaxf(vp, __shfl_xor_sync(0xffffffffu, vp, 1));
                vp = fmaxf(vp, __shfl_xor_sync(0xffffffffu, vp, 2));
                vn = fminf(vn, __shfl_xor_sync(0xffffffffu, vn, 1));
                vn = fminf(vn, __shfl_xor_sync(0xffffffffu, vn, 2));
                if ((lane & 3) == 0) {
                    const int r = rbase + (q >> 1) * 16 + (q & 1) * 8;
                    atomicMax(&g_hp[r], __float_as_int(vp));
                    atomicMin(&g_hn[r], __float_as_int(vn));
                }
                hp2[q] = -1.0f; hn2[q] = BIGF;
            }
            __syncthreads();   // all warps done reading old A
            prefetch_tile(dynb, OFF_A, 0, 0, labels, it2 * TILE, tid, false);
            CP_COMMIT();
            const int rb2 = it2 * TILE + wm * 64 + (lane >> 2);
            #pragma unroll
            for (int q = 0; q < 8; q++) {
                int r = rb2 + (q >> 1) * 16 + (q & 1) * 8;
                sa_r[q] = g_sq[r];
                la_r[q] = labels[r];
            }
        }
        it = it2; jt = jt2;
    }

    // final row-side flush
    if (start < end) {
        // note: after loop, it/jt advanced once past last tile; recover last it
        int last_it = it, last_jt = jt;
        // step back one
        if (last_jt == last_it) { last_it -= 1; }   // wrapped at end of row
        const int rbase = last_it * TILE + wm * 64 + (lane >> 2);
        #pragma unroll
        for (int q = 0; q < 8; q++) {
            float vp = hp2[q], vn = hn2[q];
            vp = fmaxf(vp, __shfl_xor_sync(0xffffffffu, vp, 1));
            vp = fmaxf(vp, __shfl_xor_sync(0xffffffffu, vp, 2));
            vn = fminf(vn, __shfl_xor_sync(0xffffffffu, vn, 1));
            vn = fminf(vn, __shfl_xor_sync(0xffffffffu, vn, 2));
            if ((lane & 3) == 0) {
                const int r = rbase + (q >> 1) * 16 + (q & 1) * 8;
                atomicMax(&g_hp[r], __float_as_int(vp));
                atomicMin(&g_hn[r], __float_as_int(vn));
            }
        }
    }

    // ---- fused finalize: last CTA reduces ----
    __threadfence();
    __shared__ unsigned s_last;
    __shared__ float s_ps[8], s_pc[8];
    if (tid == 0) s_last = (atomicAdd(&g_done, 1u) == (unsigned)gridDim.x - 1u) ? 1u : 0u;
    __syncthreads();
    if (s_last) {
        __threadfence();
        float sum = 0.0f, cnt = 0.0f;
        for (int i = tid; i < n; i += 256) {
            const float hp = __int_as_float(g_hp[i]);
            const float hn = __int_as_float(g_hn[i]);
            if (hp >= 0.0f && hn < 0.5f * BIGF) {
                sum += fmaxf(sqrtf(hp) - sqrtf(hn) + MARGIN_F, 0.0f);
                cnt += 1.0f;
            }
        }
        #pragma unroll
        for (int o = 16; o; o >>= 1) {
            sum += __shfl_xor_sync(0xffffffffu, sum, o);
            cnt += __shfl_xor_sync(0xffffffffu, cnt, o);
        }
        if (lane == 0) { s_ps[warp] = sum; s_pc[warp] = cnt; }
        __syncthreads();
        if (tid == 0) {
            float ts = 0.0f, tc = 0.0f;
            #pragma unroll
            for (int w = 0; w < 8; w++) { ts += s_ps[w]; tc += s_pc[w]; }
            out[0] = (tc > 0.0f) ? (ts / tc) : 0.0f;
        }
    }
}

extern "C" void kernel_launch(void* const* d_in, const int* in_sizes, int n_in,
                              void* d_out, int out_size) {
    const float* x      = (const float*)d_in[0];
    const int*   labels = (const int*)d_in[1];
    const int    n      = in_sizes[1];     // 8192
    float*       out    = (float*)d_out;

    static int nsm = 0;                    // idempotent, host-side, capture-safe
    if (nsm == 0) {
        cudaFuncSetAttribute(gram_kernel,
                             cudaFuncAttributeMaxDynamicSharedMemorySize, SMEM_DYN);
        cudaDeviceGetAttribute(&nsm, cudaDevAttrMultiProcessorCount, 0);
        if (nsm <= 0) nsm = 148;
    }

    convert_kernel<<<n / 8, 256>>>(x, n);
    gram_kernel<<<nsm, 256, SMEM_DYN>>>(labels, n, out);
}

// round 15
// speedup vs baseline: 9.3438x; 1.1063x over previous
#include <cuda_runtime.h>
#include <cuda_fp16.h>

#define D        128
#define NMAX     8192
#define TILE     128
#define MARGIN_F 0.3f
#define BIGF     1e30f

// ---------------- device global scratch ----------------
__device__ float  g_sq[NMAX];
__device__ int    g_hp[NMAX];            // float bits of max d2 (pos)
__device__ int    g_hn[NMAX];            // float bits of min d2 (neg)
__device__ __half g_xh[NMAX * D];
__device__ unsigned g_done;

// ---------------- smem layout (bytes) ----------------
#define ROWB       272                    // 128 halves + 8 pad halves
#define TB         (TILE * ROWB)          // 34816
#define OFF_A      0
#define OFF_B0     TB
#define OFF_B1     (2 * TB)
#define OFF_SQ0    (3 * TB)
#define OFF_LB0    (3 * TB + 512)
#define OFF_SQ1    (3 * TB + 1024)
#define OFF_LB1    (3 * TB + 1536)
#define SMEM_DYN   (3 * TB + 2048)

// ---------------- PTX helpers ----------------
__device__ __forceinline__ unsigned smem_u32(const void* p) {
    unsigned a;
    asm("{ .reg .u64 t; cvta.to.shared.u64 t, %1; cvt.u32.u64 %0, t; }" : "=r"(a) : "l"(p));
    return a;
}
__device__ __forceinline__ void cp16(unsigned dst, const void* src) {
    asm volatile("cp.async.cg.shared.global [%0], [%1], 16;" :: "r"(dst), "l"(src));
}
__device__ __forceinline__ void cp4(unsigned dst, const void* src) {
    asm volatile("cp.async.ca.shared.global [%0], [%1], 4;" :: "r"(dst), "l"(src));
}
#define CP_COMMIT() asm volatile("cp.async.commit_group;" ::: "memory")
#define CP_WAIT0()  asm volatile("cp.async.wait_group 0;" ::: "memory")

__device__ __forceinline__ void ldsm_x4(unsigned r[4], unsigned addr) {
    asm volatile("ldmatrix.sync.aligned.m8n8.x4.shared.b16 {%0,%1,%2,%3}, [%4];"
                 : "=r"(r[0]), "=r"(r[1]), "=r"(r[2]), "=r"(r[3]) : "r"(addr));
}
__device__ __forceinline__ void mma16816(float c[4], const unsigned a[4],
                                         unsigned b0, unsigned b1) {
    asm volatile(
        "mma.sync.aligned.m16n8k16.row.col.f32.f16.f16.f32 "
        "{%0,%1,%2,%3}, {%4,%5,%6,%7}, {%8,%9}, {%0,%1,%2,%3};"
        : "+f"(c[0]), "+f"(c[1]), "+f"(c[2]), "+f"(c[3])
        : "r"(a[0]), "r"(a[1]), "r"(a[2]), "r"(a[3]), "r"(b0), "r"(b1));
}

// ---------------- convert + norms + init, one kernel (warp per row) ----------
__global__ void convert_kernel(const float* __restrict__ x, int n) {
    const int row  = blockIdx.x * 8 + (threadIdx.x >> 5);
    const int lane = threadIdx.x & 31;
    if (blockIdx.x == 0 && threadIdx.x == 0) g_done = 0;
    if (row < n) {
        float4 v = reinterpret_cast<const float4*>(x + (size_t)row * D)[lane];
        __half2 h0 = __floats2half2_rn(v.x, v.y);
        __half2 h1 = __floats2half2_rn(v.z, v.w);
        uint2 o;
        o.x = *reinterpret_cast<unsigned*>(&h0);
        o.y = *reinterpret_cast<unsigned*>(&h1);
        reinterpret_cast<uint2*>(g_xh + (size_t)row * D)[lane] = o;
        float2 fa = __half22float2(h0), fb = __half22float2(h1);
        float s = fa.x * fa.x + fa.y * fa.y + fb.x * fb.x + fb.y * fb.y;
        #pragma unroll
        for (int o2 = 16; o2; o2 >>= 1) s += __shfl_xor_sync(0xffffffffu, s, o2);
        if (lane == 0) {
            g_sq[row] = s;
            g_hp[row] = __float_as_int(-1.0f);
            g_hn[row] = __float_as_int(BIGF);
        }
    }
}

// ---------------- tile prefetch (512 threads) ----------------
__device__ __forceinline__ void prefetch_tile(unsigned dynb, int off_tile,
                                              int off_sq, int off_lb,
                                              const int* __restrict__ labels,
                                              int r0, int tid, bool scalars) {
    #pragma unroll
    for (int it = 0; it < 4; it++) {
        int c   = tid + it * 512;
        int row = c >> 4;
        int j2  = c & 15;
        cp16(dynb + off_tile + row * ROWB + j2 * 16,
             g_xh + (size_t)(r0 + row) * D + j2 * 8);
    }
    if (scalars && tid < TILE) {
        cp4(dynb + off_sq + tid * 4, &g_sq[r0 + tid]);
        cp4(dynb + off_lb + tid * 4, &labels[r0 + tid]);
    }
}

// ---------------- main persistent HMMA kernel (upper triangle) -------------
__global__ __launch_bounds__(512, 1)
void gram_kernel(const int* __restrict__ labels, int n, float* __restrict__ out) {
    extern __shared__ char dyn[];
    const unsigned dynb = smem_u32(dyn);

    const int tid  = threadIdx.x;
    const int warp = tid >> 5, lane = tid & 31;
    const int wm   = warp & 3;           // rows: wm*32
    const int wn   = warp >> 2;          // cols: wn*32

    const int NTl   = n / TILE;
    const int total = NTl * (NTl + 1) / 2;
    const int start = (int)((long long)blockIdx.x * total / gridDim.x);
    const int end   = (int)((long long)(blockIdx.x + 1) * total / gridDim.x);

    float hp2[4], hn2[4];
    #pragma unroll
    for (int q = 0; q < 4; q++) { hp2[q] = -1.0f; hn2[q] = BIGF; }

    float sa_r[4];
    int   la_r[4];

    int it = 0, jt = 0;
    if (start < end) {
        int rem = start;
        while (rem >= NTl - it) { rem -= NTl - it; it++; }
        jt = it + rem;

        prefetch_tile(dynb, OFF_A, 0, 0, labels, it * TILE, tid, false);
        prefetch_tile(dynb, OFF_B0, OFF_SQ0, OFF_LB0, labels, jt * TILE, tid, true);
        CP_COMMIT();

        const int rb = it * TILE + wm * 32 + (lane >> 2);
        #pragma unroll
        for (int q = 0; q < 4; q++) {
            int r = rb + (q >> 1) * 16 + (q & 1) * 8;
            sa_r[q] = g_sq[r];
            la_r[q] = labels[r];
        }
    }

    const unsigned a_row = (unsigned)(wm * 32 + (lane & 15));
    const unsigned a_kad = (unsigned)((lane >> 4) * 16);
    const unsigned b_row = (unsigned)(wn * 32 + ((lane >> 4) << 3) + (lane & 7));
    const unsigned b_kad = (unsigned)(((lane >> 3) & 1) * 16);

    for (int k = start; k < end; k++) {
        int it2 = it, jt2 = jt + 1;
        if (jt2 == NTl) { it2 = it + 1; jt2 = it2; }

        CP_WAIT0();
        __syncthreads();
        const int buf     = (k - start) & 1;
        const int off_bs  = buf ? OFF_B1 : OFF_B0;
        const int off_sqb = buf ? OFF_SQ1 : OFF_SQ0;
        const int off_lbb = buf ? OFF_LB1 : OFF_LB0;

        if (k + 1 < end) {
            prefetch_tile(dynb, buf ? OFF_B0 : OFF_B1,
                          buf ? OFF_SQ0 : OFF_SQ1, buf ? OFF_LB0 : OFF_LB1,
                          labels, jt2 * TILE, tid, true);
            CP_COMMIT();
        }

        // ---- MMA: 32x32 per warp, K=128 ----
        float acc[2][4][4];
        #pragma unroll
        for (int mt = 0; mt < 2; mt++)
            #pragma unroll
            for (int nt = 0; nt < 4; nt++)
                #pragma unroll
                for (int r = 0; r < 4; r++) acc[mt][nt][r] = 0.0f;

        #pragma unroll
        for (int ks = 0; ks < 8; ks++) {
            const unsigned kb = (unsigned)(ks * 32);
            unsigned a[2][4];
            #pragma unroll
            for (int mt = 0; mt < 2; mt++)
                ldsm_x4(a[mt], dynb + OFF_A + (a_row + mt * 16) * ROWB + kb + a_kad);
            unsigned b[2][4];
            #pragma unroll
            for (int bp = 0; bp < 2; bp++)
                ldsm_x4(b[bp], dynb + off_bs + (b_row + bp * 16) * ROWB + kb + b_kad);
            #pragma unroll
            for (int mt = 0; mt < 2; mt++)
                #pragma unroll
                for (int nt = 0; nt < 4; nt++)
                    mma16816(acc[mt][nt], a[mt],
                             b[nt >> 1][(nt & 1) * 2], b[nt >> 1][(nt & 1) * 2 + 1]);
        }

        // ---- epilogue ----
        const float* sqB = reinterpret_cast<const float*>(dyn + off_sqb);
        const int*   lbB = reinterpret_cast<const int*>(dyn + off_lbb);
        float sb[8]; int lbr[8];
        #pragma unroll
        for (int nt = 0; nt < 4; nt++)
            #pragma unroll
            for (int u = 0; u < 2; u++) {
                int cl = wn * 32 + nt * 8 + 2 * (lane & 3) + u;
                sb[nt * 2 + u]  = sqB[cl];
                lbr[nt * 2 + u] = lbB[cl];
            }
        const int rbase = it * TILE + wm * 32 + (lane >> 2);
        const int j0g   = jt * TILE;

        if (it == jt) {
            // diagonal: row-side only, mask self pairs
            #pragma unroll
            for (int mt = 0; mt < 2; mt++)
                #pragma unroll
                for (int h = 0; h < 2; h++) {
                    const int   q  = mt * 2 + h;
                    const float sa = sa_r[q];
                    const int   la = la_r[q];
                    const int   ig = rbase + mt * 16 + h * 8;
                    #pragma unroll
                    for (int nt = 0; nt < 4; nt++)
                        #pragma unroll
                        for (int u = 0; u < 2; u++) {
                            const float d2 = fmaxf(
                                fmaf(-2.0f, acc[mt][nt][h * 2 + u], sa + sb[nt * 2 + u]), 0.0f);
                            const int cl = wn * 32 + nt * 8 + 2 * (lane & 3) + u;
                            if (j0g + cl != ig) {
                                if (lbr[nt * 2 + u] == la) hp2[q] = fmaxf(hp2[q], d2);
                                else                       hn2[q] = fminf(hn2[q], d2);
                            }
                        }
                }
        } else {
            // off-diagonal: row-side registers + column-side reduce/atomics
            float cp2[8], cn2[8];
            #pragma unroll
            for (int e = 0; e < 8; e++) { cp2[e] = -1.0f; cn2[e] = BIGF; }
            #pragma unroll
            for (int mt = 0; mt < 2; mt++)
                #pragma unroll
                for (int h = 0; h < 2; h++) {
                    const int   q  = mt * 2 + h;
                    const float sa = sa_r[q];
                    const int   la = la_r[q];
                    #pragma unroll
                    for (int nt = 0; nt < 4; nt++)
                        #pragma unroll
                        for (int u = 0; u < 2; u++) {
                            const int   e  = nt * 2 + u;
                            const float d2 = fmaxf(
                                fmaf(-2.0f, acc[mt][nt][h * 2 + u], sa + sb[e]), 0.0f);
                            if (lbr[e] == la) {
                                hp2[q] = fmaxf(hp2[q], d2);
                                cp2[e] = fmaxf(cp2[e], d2);
                            } else {
                                hn2[q] = fminf(hn2[q], d2);
                                cn2[e] = fminf(cn2[e], d2);
                            }
                        }
                }
            // reduce col-side over the 8 row-lane groups (stride 4,8,16)
            #pragma unroll
            for (int s = 4; s <= 16; s <<= 1)
                #pragma unroll
                for (int e = 0; e < 8; e++) {
                    cp2[e] = fmaxf(cp2[e], __shfl_xor_sync(0xffffffffu, cp2[e], s));
                    cn2[e] = fminf(cn2[e], __shfl_xor_sync(0xffffffffu, cn2[e], s));
                }
            if ((lane >> 2) == 0) {
                #pragma unroll
                for (int nt = 0; nt < 4; nt++)
                    #pragma unroll
                    for (int u = 0; u < 2; u++) {
                        const int col = j0g + wn * 32 + nt * 8 + 2 * lane + u;
                        atomicMax(&g_hp[col], __float_as_int(cp2[nt * 2 + u]));
                        atomicMin(&g_hn[col], __float_as_int(cn2[nt * 2 + u]));
                    }
            }
        }

        // i-tile change: flush row-side, reload A + row scalars
        if (k + 1 < end && it2 != it) {
            #pragma unroll
            for (int q = 0; q < 4; q++) {
                float vp = hp2[q], vn = hn2[q];
                vp = fmaxf(vp, __shfl_xor_sync(0xffffffffu, vp, 1));
                vp = fmaxf(vp, __shfl_xor_sync(0xffffffffu, vp, 2));
                vn = fminf(vn, __shfl_xor_sync(0xffffffffu, vn, 1));
                vn = fminf(vn, __shfl_xor_sync(0xffffffffu, vn, 2));
                if ((lane & 3) == 0) {
                    const int r = rbase + (q >> 1) * 16 + (q & 1) * 8;
                    atomicMax(&g_hp[r], __float_as_int(vp));
                    atomicMin(&g_hn[r], __float_as_int(vn));
                }
                hp2[q] = -1.0f; hn2[q] = BIGF;
            }
            __syncthreads();   // all warps done reading old A
            prefetch_tile(dynb, OFF_A, 0, 0, labels, it2 * TILE, tid, false);
            CP_COMMIT();
            const int rb2 = it2 * TILE + wm * 32 + (lane >> 2);
            #pragma unroll
            for (int q = 0; q < 4; q++) {
                int r = rb2 + (q >> 1) * 16 + (q & 1) * 8;
                sa_r[q] = g_sq[r];
                la_r[q] = labels[r];
            }
        }
        it = it2; jt = jt2;
    }

    // final row-side flush
    if (start < end) {
        int last_it = it, last_jt = jt;
        if (last_jt == last_it) { last_it -= 1; }   // wrapped at end of row
        const int rbase = last_it * TILE + wm * 32 + (lane >> 2);
        #pragma unroll
        for (int q = 0; q < 4; q++) {
            float vp = hp2[q], vn = hn2[q];
            vp = fmaxf(vp, __shfl_xor_sync(0xffffffffu, vp, 1));
            vp = fmaxf(vp, __shfl_xor_sync(0xffffffffu, vp, 2));
            vn = fminf(vn, __shfl_xor_sync(0xffffffffu, vn, 1));
            vn = fminf(vn, __shfl_xor_sync(0xffffffffu, vn, 2));
            if ((lane & 3) == 0) {
                const int r = rbase + (q >> 1) * 16 + (q & 1) * 8;
                atomicMax(&g_hp[r], __float_as_int(vp));
                atomicMin(&g_hn[r], __float_as_int(vn));
            }
        }
    }

    // ---- fused finalize: last CTA reduces ----
    __threadfence();
    __shared__ unsigned s_last;
    __shared__ float s_ps[16], s_pc[16];
    if (tid == 0) s_last = (atomicAdd(&g_done, 1u) == (unsigned)gridDim.x - 1u) ? 1u : 0u;
    __syncthreads();
    if (s_last) {
        __threadfence();
        float sum = 0.0f, cnt = 0.0f;
        for (int i = tid; i < n; i += 512) {
            const float hp = __int_as_float(g_hp[i]);
            const float hn = __int_as_float(g_hn[i]);
            if (hp >= 0.0f && hn < 0.5f * BIGF) {
                sum += fmaxf(sqrtf(hp) - sqrtf(hn) + MARGIN_F, 0.0f);
                cnt += 1.0f;
            }
        }
        #pragma unroll
        for (int o = 16; o; o >>= 1) {
            sum += __shfl_xor_sync(0xffffffffu, sum, o);
            cnt += __shfl_xor_sync(0xffffffffu, cnt, o);
        }
        if (lane == 0) { s_ps[warp] = sum; s_pc[warp] = cnt; }
        __syncthreads();
        if (tid == 0) {
            float ts = 0.0f, tc = 0.0f;
            #pragma unroll
            for (int w = 0; w < 16; w++) { ts += s_ps[w]; tc += s_pc[w]; }
            out[0] = (tc > 0.0f) ? (ts / tc) : 0.0f;
        }
    }
}

extern "C" void kernel_launch(void* const* d_in, const int* in_sizes, int n_in,
                              void* d_out, int out_size) {
    const float* x      = (const float*)d_in[0];
    const int*   labels = (const int*)d_in[1];
    const int    n      = in_sizes[1];     // 8192
    float*       out    = (float*)d_out;

    static int nsm = 0;                    // idempotent, host-side, capture-safe
    if (nsm == 0) {
        cudaFuncSetAttribute(gram_kernel,
                             cudaFuncAttributeMaxDynamicSharedMemorySize, SMEM_DYN);
        cudaDeviceGetAttribute(&nsm, cudaDevAttrMultiProcessorCount, 0);
        if (nsm <= 0) nsm = 148;
    }

    convert_kernel<<<n / 8, 256>>>(x, n);
    gram_kernel<<<nsm, 512, SMEM_DYN>>>(labels, n, out);
}